// round 4
// baseline (speedup 1.0000x reference)
#include <cuda_runtime.h>
#include <math.h>

#define C_    192
#define NHEAD 6
#define HDIM  32
#define NTOK  (32*64*64)        // 131072
#define QKVW  (3*C_)            // 576
#define MLPD  (4*C_)            // 768

// ---------------- static scratch ----------------
__device__ float g_YZ  [NTOK*C_];      // Y (LN1 out), later Z (LN2 out)
__device__ float g_QKV [NTOK*QKVW];
__device__ float g_XMID[NTOK*C_];
__device__ float g_H   [NTOK*MLPD];    // front NTOK*C_ doubles as AO before phase 6

// ---------------- helpers ----------------
__device__ __forceinline__ unsigned f2tf32(float x) {
    unsigned r; asm("cvt.rna.tf32.f32 %0, %1;" : "=r"(r) : "f"(x)); return r;
}
__device__ __forceinline__ void mma_tf32(float* c, const unsigned* a, const unsigned* b) {
    asm volatile("mma.sync.aligned.m16n8k8.row.col.f32.tf32.tf32.f32 "
        "{%0,%1,%2,%3}, {%4,%5,%6,%7}, {%8,%9}, {%0,%1,%2,%3};"
        : "+f"(c[0]), "+f"(c[1]), "+f"(c[2]), "+f"(c[3])
        : "r"(a[0]), "r"(a[1]), "r"(a[2]), "r"(a[3]), "r"(b[0]), "r"(b[1]));
}

// ---------------- LayerNorm (one warp per token) ----------------
template<bool WINDOWED>
__global__ __launch_bounds__(256) void ln_kernel(
        const float* __restrict__ x,
        const float* __restrict__ gamma,
        const float* __restrict__ beta,
        float* __restrict__ y) {
    int warp = (blockIdx.x * blockDim.x + threadIdx.x) >> 5;
    int lane = threadIdx.x & 31;
    if (warp >= NTOK) return;

    long src;
    if (WINDOWED) {
        int p   = warp & 63;
        int win = (warp >> 6) & 63;
        int b   = warp >> 12;
        int r = p >> 3, c = p & 7;
        int wi = win >> 3, wj = win & 7;
        int h = (wi*8 + r + 4) & 63;
        int w = (wj*8 + c + 4) & 63;
        src = (long)((b*64 + h)*64 + w);
    } else {
        src = warp;
    }
    const float* xr = x + src * C_;
    float v[6];
    float s = 0.f;
#pragma unroll
    for (int i = 0; i < 6; i++) { v[i] = xr[lane + 32*i]; s += v[i]; }
#pragma unroll
    for (int o = 16; o; o >>= 1) s += __shfl_xor_sync(0xffffffffu, s, o);
    float mean = s * (1.f / C_);
    float q = 0.f;
#pragma unroll
    for (int i = 0; i < 6; i++) { float d = v[i] - mean; q += d*d; }
#pragma unroll
    for (int o = 16; o; o >>= 1) q += __shfl_xor_sync(0xffffffffu, q, o);
    float inv = rsqrtf(q * (1.f / C_) + 1e-5f);

    float* yr = y + (long)warp * C_;
#pragma unroll
    for (int i = 0; i < 6; i++) {
        int ch = lane + 32*i;
        yr[ch] = (v[i] - mean) * inv * gamma[ch] + beta[ch];
    }
}

// ---------------- tf32 tensor-core GEMM: C[M,N] = A[M,K] @ W[N,K]^T (+epilogue) ----------------
// BM=128, BN=64, BK=16, double-buffered smem, interleaved k-layout so each
// mma fragment pair (k=t, k=t+4) is one LDS.64.
// 256 threads = 8 warps (4m x 2n), warp tile 32x32.
// EPI: 0=+bias  1=+bias,unwindow+residual  2=+bias,GELU  3=+bias,residual
#define BKg 16
#define SW  24   // smem row stride in words (conflict-free for the LDS.64 pattern)
template<int EPI>
__global__ __launch_bounds__(256, 2) void gemm_tc(
        const float* __restrict__ A, const float* __restrict__ W,
        const float* __restrict__ bias, const float* __restrict__ res,
        float* __restrict__ out, int M, int N, int K) {
    __shared__ unsigned As[2][128*SW];
    __shared__ unsigned Bs[2][64*SW];

    int tid  = threadIdx.x;
    int lane = tid & 31;
    int wid  = tid >> 5;
    int wm   = wid >> 1;     // 0..3
    int wn   = wid & 1;      // 0..1
    int g    = lane >> 2;    // 0..7
    int t    = lane & 3;     // 0..3

    int n0   = blockIdx.x * 64;
    long m0  = (long)blockIdx.y * 128;
    int nit  = K / BKg;

    // global-load index precompute (A: 2 float4/thread, B: 1 float4/thread)
    // interleave: within each 8-k group, phys(kv) = 2*(kv&3) + (kv>>2)
    int am[2], abase[2], bn, bbase;
#pragma unroll
    for (int i = 0; i < 2; i++) {
        int idx = tid + 256*i;
        am[i] = idx >> 2;
        int ak = (idx & 3) * 4;                 // 0,4,8,12
        abase[i] = am[i]*SW + (ak & 8) + ((ak & 4) ? 1 : 0);
    }
    {
        bn = tid >> 2;
        int bk = (tid & 3) * 4;
        bbase = bn*SW + (bk & 8) + ((bk & 4) ? 1 : 0);
    }

    float4 pa[2], pb;
    auto load_tile = [&](int k0) {
#pragma unroll
        for (int i = 0; i < 2; i++)
            pa[i] = *(const float4*)(A + (m0 + am[i]) * (long)K + k0 + ((tid + 256*i) & 3) * 4);
        pb = *(const float4*)(W + (long)(n0 + bn) * K + k0 + (tid & 3) * 4);
    };
    auto store_tile = [&](int s) {
#pragma unroll
        for (int i = 0; i < 2; i++) {
            unsigned* d = &As[s][abase[i]];
            d[0]=f2tf32(pa[i].x); d[2]=f2tf32(pa[i].y); d[4]=f2tf32(pa[i].z); d[6]=f2tf32(pa[i].w);
        }
        {
            unsigned* d = &Bs[s][bbase];
            d[0]=f2tf32(pb.x); d[2]=f2tf32(pb.y); d[4]=f2tf32(pb.z); d[6]=f2tf32(pb.w);
        }
    };

    float acc[2][4][4];
#pragma unroll
    for (int i = 0; i < 2; i++)
#pragma unroll
        for (int j = 0; j < 4; j++)
#pragma unroll
            for (int k = 0; k < 4; k++) acc[i][j][k] = 0.f;

    load_tile(0);
    store_tile(0);
    __syncthreads();

    for (int it = 0; it < nit; it++) {
        int cur = it & 1;
        bool more = (it + 1 < nit);
        if (more) load_tile((it + 1) * BKg);

        const unsigned* Ac = As[cur];
        const unsigned* Bc = Bs[cur];
#pragma unroll
        for (int ks = 0; ks < 2; ks++) {
            int kb = ks * 8 + 2*t;
            unsigned af[2][4], bf[4][2];
#pragma unroll
            for (int mi = 0; mi < 2; mi++) {
                int mr = wm*32 + mi*16 + g;
                uint2 lo = *(const uint2*)&Ac[ mr     *SW + kb];
                uint2 hi = *(const uint2*)&Ac[(mr + 8)*SW + kb];
                af[mi][0] = lo.x; af[mi][1] = hi.x; af[mi][2] = lo.y; af[mi][3] = hi.y;
            }
#pragma unroll
            for (int ni = 0; ni < 4; ni++) {
                int nr = wn*32 + ni*8 + g;
                uint2 bv = *(const uint2*)&Bc[nr*SW + kb];
                bf[ni][0] = bv.x; bf[ni][1] = bv.y;
            }
#pragma unroll
            for (int mi = 0; mi < 2; mi++)
#pragma unroll
                for (int ni = 0; ni < 4; ni++)
                    mma_tf32(acc[mi][ni], af[mi], bf[ni]);
        }
        if (more) {
            store_tile(cur ^ 1);
            __syncthreads();
        }
    }

    // ---------------- epilogue ----------------
#pragma unroll
    for (int mi = 0; mi < 2; mi++) {
#pragma unroll
        for (int half = 0; half < 2; half++) {
            long m = m0 + wm*32 + mi*16 + g + half*8;
            long orow;
            if (EPI == 1) {
                int p   = (int)(m & 63);
                int win = (int)((m >> 6) & 63);
                int b   = (int)(m >> 12);
                int r = p >> 3, c = p & 7;
                int wi = win >> 3, wj = win & 7;
                int h = (wi*8 + r + 4) & 63;
                int w = (wj*8 + c + 4) & 63;
                orow = (long)((b*64 + h)*64 + w);
            } else {
                orow = m;
            }
#pragma unroll
            for (int ni = 0; ni < 4; ni++) {
                int col = n0 + wn*32 + ni*8 + t*2;
                float v0 = acc[mi][ni][half*2 + 0] + __ldg(bias + col);
                float v1 = acc[mi][ni][half*2 + 1] + __ldg(bias + col + 1);
                if (EPI == 1) {
                    const float2 rv = *(const float2*)(res + orow * (long)N + col);
                    v0 += rv.x; v1 += rv.y;
                } else if (EPI == 2) {
                    v0 = 0.5f * v0 * (1.f + erff(v0 * 0.70710678118654752f));
                    v1 = 0.5f * v1 * (1.f + erff(v1 * 0.70710678118654752f));
                } else if (EPI == 3) {
                    const float2 rv = *(const float2*)(res + m * (long)N + col);
                    v0 += rv.x; v1 += rv.y;
                }
                *(float2*)(out + orow * (long)N + col) = make_float2(v0, v1);
            }
        }
    }
}

// ---------------- windowed attention: one block per (window, head), 64 threads ----------------
__global__ __launch_bounds__(64) void attn_kernel(
        const float* __restrict__ qkv,
        const float* __restrict__ rpp,
        float* __restrict__ ao) {
    int wg   = blockIdx.x;
    int head = blockIdx.y;
    int t    = threadIdx.x;
    int win  = wg & 63;
    int wi = win >> 3, wj = win & 7;

    __shared__ float ks[64][36];
    __shared__ float vs[64][36];
    __shared__ float S[64][65];
    __shared__ float biasS[228];

    long rowbase = (long)(wg*64 + t) * QKVW;
    float q[32];
    {
        const float4* qp = (const float4*)(qkv + rowbase + head*HDIM);
        const float4* kp = (const float4*)(qkv + rowbase + (NHEAD + head)*HDIM);
        const float4* vp = (const float4*)(qkv + rowbase + (2*NHEAD + head)*HDIM);
#pragma unroll
        for (int d4 = 0; d4 < 8; d4++) {
            float4 qv = qp[d4];
            q[4*d4+0] = qv.x; q[4*d4+1] = qv.y; q[4*d4+2] = qv.z; q[4*d4+3] = qv.w;
            ((float4*)&ks[t][0])[d4] = kp[d4];
            ((float4*)&vs[t][0])[d4] = vp[d4];
        }
    }
    for (int i = t; i < 225; i += 64) biasS[i] = rpp[head*225 + i];
    __syncthreads();

    const float scale = 0.17677669529663687f;
    int r1 = t >> 3, c1 = t & 7;
    bool mi = (wi == 7), mj = (wj == 7);
    bool q_r = (r1 < 4), q_c = (c1 < 4);

    float mx = -1e30f;
#pragma unroll 4
    for (int j = 0; j < 64; j++) {
        int r2 = j >> 3, c2 = j & 7;
        const float4* kr = (const float4*)&ks[j][0];
        float s = 0.f;
#pragma unroll
        for (int d4 = 0; d4 < 8; d4++) {
            float4 kv = kr[d4];
            s += q[4*d4+0]*kv.x + q[4*d4+1]*kv.y + q[4*d4+2]*kv.z + q[4*d4+3]*kv.w;
        }
        s = s * scale + biasS[(r1 - r2 + 7)*15 + (c1 - c2 + 7)];
        bool msk = (mi && (q_r != (r2 < 4))) || (mj && (q_c != (c2 < 4)));
        if (msk) s = -1e30f;
        S[t][j] = s;
        mx = fmaxf(mx, s);
    }
    float sum = 0.f;
#pragma unroll 4
    for (int j = 0; j < 64; j++) {
        float p = __expf(S[t][j] - mx);
        S[t][j] = p;
        sum += p;
    }
    float o[32] = {};
#pragma unroll 2
    for (int j = 0; j < 64; j++) {
        float p = S[t][j];
        const float4* vr = (const float4*)&vs[j][0];
#pragma unroll
        for (int d4 = 0; d4 < 8; d4++) {
            float4 vv = vr[d4];
            o[4*d4+0] += p*vv.x; o[4*d4+1] += p*vv.y;
            o[4*d4+2] += p*vv.z; o[4*d4+3] += p*vv.w;
        }
    }
    float inv = 1.f / sum;
    float* orow = ao + (long)(wg*64 + t) * C_ + head*HDIM;
#pragma unroll
    for (int d4 = 0; d4 < 8; d4++) {
        float4 ov = make_float4(o[4*d4]*inv, o[4*d4+1]*inv, o[4*d4+2]*inv, o[4*d4+3]*inv);
        ((float4*)orow)[d4] = ov;
    }
}

// ---------------- launcher ----------------
extern "C" void kernel_launch(void* const* d_in, const int* in_sizes, int n_in,
                              void* d_out, int out_size) {
    const float* x      = (const float*)d_in[0];
    const float* ln1_g  = (const float*)d_in[1];
    const float* ln1_b  = (const float*)d_in[2];
    const float* qkv_w  = (const float*)d_in[3];
    const float* qkv_b  = (const float*)d_in[4];
    const float* rpp    = (const float*)d_in[5];
    const float* lin_w  = (const float*)d_in[6];
    const float* lin_b  = (const float*)d_in[7];
    const float* ln2_g  = (const float*)d_in[8];
    const float* ln2_b  = (const float*)d_in[9];
    const float* mlp_w1 = (const float*)d_in[10];
    const float* mlp_b1 = (const float*)d_in[11];
    const float* mlp_w2 = (const float*)d_in[12];
    const float* mlp_b2 = (const float*)d_in[13];
    float* out = (float*)d_out;

    float *YZ, *QKV, *XMID, *Hm;
    cudaGetSymbolAddress((void**)&YZ,   g_YZ);
    cudaGetSymbolAddress((void**)&QKV,  g_QKV);
    cudaGetSymbolAddress((void**)&XMID, g_XMID);
    cudaGetSymbolAddress((void**)&Hm,   g_H);
    float* AO = Hm;

    const int LN_BLOCKS = NTOK / 8;
    const int MBT = NTOK / 128;     // 1024 row tiles

    // 1) LN1 + shift-roll + window partition
    ln_kernel<true><<<LN_BLOCKS, 256>>>(x, ln1_g, ln1_b, YZ);
    // 2) qkv projection (+bias)
    gemm_tc<0><<<dim3(QKVW/64, MBT), 256>>>(YZ, qkv_w, qkv_b, nullptr, QKV, NTOK, QKVW, C_);
    // 3) windowed attention
    attn_kernel<<<dim3(2048, NHEAD), 64>>>(QKV, rpp, AO);
    // 4) output projection + un-window/un-roll + residual
    gemm_tc<1><<<dim3(C_/64, MBT), 256>>>(AO, lin_w, lin_b, x, XMID, NTOK, C_, C_);
    // 5) LN2
    ln_kernel<false><<<LN_BLOCKS, 256>>>(XMID, ln2_g, ln2_b, YZ);
    // 6) MLP up + exact GELU
    gemm_tc<2><<<dim3(MLPD/64, MBT), 256>>>(YZ, mlp_w1, mlp_b1, nullptr, Hm, NTOK, MLPD, C_);
    // 7) MLP down + residual -> out
    gemm_tc<3><<<dim3(C_/64, MBT), 256>>>(Hm, mlp_w2, mlp_b2, XMID, out, NTOK, C_, MLPD);
}

// round 5
// speedup vs baseline: 2.1188x; 2.1188x over previous
#include <cuda_runtime.h>
#include <cuda_bf16.h>
#include <math.h>

#define C_    192
#define NHEAD 6
#define HDIM  32
#define NTOK  (32*64*64)        // 131072
#define QKVW  (3*C_)            // 576
#define MLPD  (4*C_)            // 768

#define W_QKV_OFF 0
#define W_LIN_OFF (QKVW*C_)                    // 110592
#define W_M1_OFF  (W_LIN_OFF + C_*C_)          // 147456
#define W_M2_OFF  (W_M1_OFF + MLPD*C_)         // 294912
#define W_TOTAL   (W_M2_OFF + C_*MLPD)         // 442368

// ---------------- static scratch ----------------
__device__ __nv_bfloat16 g_YZ  [NTOK*C_];      // Y (LN1 out), later Z (LN2 out)
__device__ __nv_bfloat16 g_QKV [NTOK*QKVW];
__device__ float         g_XMID[NTOK*C_];      // fp32 residual mid
__device__ __nv_bfloat16 g_H   [NTOK*MLPD];    // front NTOK*C_ doubles as AO earlier
__device__ __nv_bfloat16 g_Wb  [W_TOTAL];      // bf16 weights

// ---------------- helpers ----------------
__device__ __forceinline__ unsigned smem_u32(const void* p) {
    return (unsigned)__cvta_generic_to_shared(p);
}
__device__ __forceinline__ void cp16(unsigned dst, const void* src) {
    asm volatile("cp.async.cg.shared.global [%0], [%1], 16;" :: "r"(dst), "l"(src));
}
__device__ __forceinline__ void ldsm4(unsigned* r, unsigned addr) {
    asm volatile("ldmatrix.sync.aligned.m8n8.x4.shared.b16 {%0,%1,%2,%3}, [%4];"
        : "=r"(r[0]), "=r"(r[1]), "=r"(r[2]), "=r"(r[3]) : "r"(addr));
}
__device__ __forceinline__ void mma_bf16(float* c, const unsigned* a, const unsigned* b) {
    asm volatile("mma.sync.aligned.m16n8k16.row.col.f32.bf16.bf16.f32 "
        "{%0,%1,%2,%3}, {%4,%5,%6,%7}, {%8,%9}, {%0,%1,%2,%3};"
        : "+f"(c[0]), "+f"(c[1]), "+f"(c[2]), "+f"(c[3])
        : "r"(a[0]), "r"(a[1]), "r"(a[2]), "r"(a[3]), "r"(b[0]), "r"(b[1]));
}
__device__ __forceinline__ void st_pair(float* p, float v0, float v1) {
    *(float2*)p = make_float2(v0, v1);
}
__device__ __forceinline__ void st_pair(__nv_bfloat16* p, float v0, float v1) {
    *(__nv_bfloat162*)p = __floats2bfloat162_rn(v0, v1);
}

// ---------------- weight fp32->bf16 convert ----------------
__global__ __launch_bounds__(256) void cvt_kernel(const float* __restrict__ s,
                                                  __nv_bfloat16* __restrict__ d, int n) {
    int i = blockIdx.x * blockDim.x + threadIdx.x;
    if (i < n) d[i] = __float2bfloat16(s[i]);
}

// ---------------- LayerNorm (one warp per token), bf16 output ----------------
template<bool WINDOWED>
__global__ __launch_bounds__(256) void ln_kernel(
        const float* __restrict__ x,
        const float* __restrict__ gamma,
        const float* __restrict__ beta,
        __nv_bfloat16* __restrict__ y) {
    int warp = (blockIdx.x * blockDim.x + threadIdx.x) >> 5;
    int lane = threadIdx.x & 31;
    if (warp >= NTOK) return;

    long src;
    if (WINDOWED) {
        int p   = warp & 63;
        int win = (warp >> 6) & 63;
        int b   = warp >> 12;
        int r = p >> 3, c = p & 7;
        int wi = win >> 3, wj = win & 7;
        int h = (wi*8 + r + 4) & 63;
        int w = (wj*8 + c + 4) & 63;
        src = (long)((b*64 + h)*64 + w);
    } else {
        src = warp;
    }
    const float* xr = x + src * C_;
    float v[6];
    float s = 0.f;
#pragma unroll
    for (int i = 0; i < 6; i++) { v[i] = xr[lane + 32*i]; s += v[i]; }
#pragma unroll
    for (int o = 16; o; o >>= 1) s += __shfl_xor_sync(0xffffffffu, s, o);
    float mean = s * (1.f / C_);
    float q = 0.f;
#pragma unroll
    for (int i = 0; i < 6; i++) { float d = v[i] - mean; q += d*d; }
#pragma unroll
    for (int o = 16; o; o >>= 1) q += __shfl_xor_sync(0xffffffffu, q, o);
    float inv = rsqrtf(q * (1.f / C_) + 1e-5f);

    __nv_bfloat16* yr = y + (long)warp * C_;
#pragma unroll
    for (int i = 0; i < 6; i++) {
        int ch = lane + 32*i;
        yr[ch] = __float2bfloat16((v[i] - mean) * inv * gamma[ch] + beta[ch]);
    }
}

// ---------------- bf16 tensor-core GEMM: C[M,N] = A[M,K] @ W[N,K]^T (+epilogue) ----------------
// BM=128, BN=64, BK=64 (128B rows), 2-stage cp.async pipeline, XOR-swizzled smem,
// ldmatrix.x4 fragments, mma.m16n8k16.bf16.
// 256 threads = 8 warps (4m x 2n), warp tile 32x32.
// EPI: 0=+bias->bf16   1=+bias,unwindow,+res->fp32   2=+bias,GELU->bf16   3=+bias,+res->fp32
#define BK 64
template<int EPI, typename OT>
__global__ __launch_bounds__(256) void gemm_bf16(
        const __nv_bfloat16* __restrict__ A, const __nv_bfloat16* __restrict__ W,
        const float* __restrict__ bias, const float* __restrict__ res,
        OT* __restrict__ out, int M, int N, int K) {
    __shared__ __nv_bfloat16 As[2][128][BK];   // 32 KB
    __shared__ __nv_bfloat16 Bs[2][64][BK];    // 16 KB

    int tid  = threadIdx.x;
    int lane = tid & 31;
    int wid  = tid >> 5;
    int wm   = wid >> 1;     // 0..3
    int wn   = wid & 1;      // 0..1
    int g    = lane >> 2;    // 0..7
    int t    = lane & 3;     // 0..3
    int xr   = lane & 7;

    int n0   = blockIdx.x * 64;
    long m0  = (long)blockIdx.y * 128;
    int nit  = K / BK;

    // ldmatrix per-lane geometry
    int rowA = wm*32 + (lane & 7) + ((lane >> 3) & 1) * 8;   // + mi*16
    int chA  = lane >> 4;                                     // k-chunk half for tiles 2,3
    int rowB = wn*32 + (lane & 7) + (lane >> 4) * 8;          // + np*16
    int chB  = (lane >> 3) & 1;

    auto prefetch = [&](int it, int s) {
        int k0 = it * BK;
#pragma unroll
        for (int i = 0; i < 4; i++) {              // A: 128 rows x 8 chunks
            int idx = tid + 256*i;
            int r = idx >> 3, c = idx & 7;
            cp16(smem_u32(&As[s][r][((c ^ (r & 7)) * 8)]),
                 A + (m0 + r) * (long)K + k0 + c*8);
        }
#pragma unroll
        for (int i = 0; i < 2; i++) {              // B: 64 rows x 8 chunks
            int idx = tid + 256*i;
            int r = idx >> 3, c = idx & 7;
            cp16(smem_u32(&Bs[s][r][((c ^ (r & 7)) * 8)]),
                 W + (long)(n0 + r) * K + k0 + c*8);
        }
        asm volatile("cp.async.commit_group;" ::: "memory");
    };

    float acc[2][4][4];
#pragma unroll
    for (int i = 0; i < 2; i++)
#pragma unroll
        for (int j = 0; j < 4; j++)
#pragma unroll
            for (int k = 0; k < 4; k++) acc[i][j][k] = 0.f;

    prefetch(0, 0);
    prefetch(1, 1);

    for (int it = 0; it < nit; it++) {
        int cur = it & 1;
        if (it < nit - 1) asm volatile("cp.async.wait_group 1;" ::: "memory");
        else              asm volatile("cp.async.wait_group 0;" ::: "memory");
        __syncthreads();

        unsigned baseA = smem_u32(&As[cur][0][0]);
        unsigned baseB = smem_u32(&Bs[cur][0][0]);
#pragma unroll
        for (int ks = 0; ks < 4; ks++) {
            unsigned a[2][4], b[2][4];
#pragma unroll
            for (int mi = 0; mi < 2; mi++)
                ldsm4(a[mi], baseA + (unsigned)((rowA + mi*16) * (BK*2))
                                   + (unsigned)((((2*ks + chA) ^ xr) * 16)));
#pragma unroll
            for (int np = 0; np < 2; np++)
                ldsm4(b[np], baseB + (unsigned)((rowB + np*16) * (BK*2))
                                   + (unsigned)((((2*ks + chB) ^ xr) * 16)));
#pragma unroll
            for (int mi = 0; mi < 2; mi++)
#pragma unroll
                for (int ni = 0; ni < 4; ni++)
                    mma_bf16(acc[mi][ni], a[mi], &b[ni >> 1][(ni & 1) * 2]);
        }
        __syncthreads();
        if (it + 2 < nit) prefetch(it + 2, cur);
    }

    // ---------------- epilogue ----------------
#pragma unroll
    for (int mi = 0; mi < 2; mi++) {
#pragma unroll
        for (int half = 0; half < 2; half++) {
            long m = m0 + wm*32 + mi*16 + g + half*8;
            long orow;
            if (EPI == 1) {
                int p   = (int)(m & 63);
                int win = (int)((m >> 6) & 63);
                int b   = (int)(m >> 12);
                int r = p >> 3, c = p & 7;
                int wi = win >> 3, wj = win & 7;
                int h = (wi*8 + r + 4) & 63;
                int w = (wj*8 + c + 4) & 63;
                orow = (long)((b*64 + h)*64 + w);
            } else {
                orow = m;
            }
#pragma unroll
            for (int ni = 0; ni < 4; ni++) {
                int col = n0 + wn*32 + ni*8 + t*2;
                float v0 = acc[mi][ni][half*2 + 0] + __ldg(bias + col);
                float v1 = acc[mi][ni][half*2 + 1] + __ldg(bias + col + 1);
                if (EPI == 1) {
                    const float2 rv = *(const float2*)(res + orow * (long)N + col);
                    v0 += rv.x; v1 += rv.y;
                } else if (EPI == 2) {
                    v0 = 0.5f * v0 * (1.f + erff(v0 * 0.70710678118654752f));
                    v1 = 0.5f * v1 * (1.f + erff(v1 * 0.70710678118654752f));
                } else if (EPI == 3) {
                    const float2 rv = *(const float2*)(res + m * (long)N + col);
                    v0 += rv.x; v1 += rv.y;
                }
                st_pair(out + orow * (long)N + col, v0, v1);
            }
        }
    }
}

// ---------------- windowed attention (bf16 I/O, fp32 math) ----------------
__global__ __launch_bounds__(64) void attn_kernel(
        const __nv_bfloat16* __restrict__ qkv,
        const float* __restrict__ rpp,
        __nv_bfloat16* __restrict__ ao) {
    int wg   = blockIdx.x;
    int head = blockIdx.y;
    int t    = threadIdx.x;
    int win  = wg & 63;
    int wi = win >> 3, wj = win & 7;

    __shared__ float ks[64][36];
    __shared__ float vs[64][36];
    __shared__ float S[64][65];
    __shared__ float biasS[228];

    long rowbase = (long)(wg*64 + t) * QKVW;
    float q[32];
    {
        const uint4* qp = (const uint4*)(qkv + rowbase + head*HDIM);
        const uint4* kp = (const uint4*)(qkv + rowbase + (NHEAD + head)*HDIM);
        const uint4* vp = (const uint4*)(qkv + rowbase + (2*NHEAD + head)*HDIM);
#pragma unroll
        for (int i = 0; i < 4; i++) {      // 4 x 16B = 32 bf16
            uint4 qu = qp[i], ku = kp[i], vu = vp[i];
            unsigned qs[4] = {qu.x, qu.y, qu.z, qu.w};
            unsigned kk[4] = {ku.x, ku.y, ku.z, ku.w};
            unsigned vv[4] = {vu.x, vu.y, vu.z, vu.w};
#pragma unroll
            for (int j = 0; j < 4; j++) {
                float2 qf = __bfloat1622float2(*(__nv_bfloat162*)&qs[j]);
                float2 kf = __bfloat1622float2(*(__nv_bfloat162*)&kk[j]);
                float2 vf = __bfloat1622float2(*(__nv_bfloat162*)&vv[j]);
                int d = i*8 + j*2;
                q[d] = qf.x; q[d+1] = qf.y;
                ks[t][d] = kf.x; ks[t][d+1] = kf.y;
                vs[t][d] = vf.x; vs[t][d+1] = vf.y;
            }
        }
    }
    for (int i = t; i < 225; i += 64) biasS[i] = rpp[head*225 + i];
    __syncthreads();

    const float scale = 0.17677669529663687f;
    int r1 = t >> 3, c1 = t & 7;
    bool mi = (wi == 7), mj = (wj == 7);
    bool q_r = (r1 < 4), q_c = (c1 < 4);

    float mx = -1e30f;
#pragma unroll 4
    for (int j = 0; j < 64; j++) {
        int r2 = j >> 3, c2 = j & 7;
        const float4* kr = (const float4*)&ks[j][0];
        float s = 0.f;
#pragma unroll
        for (int d4 = 0; d4 < 8; d4++) {
            float4 kv = kr[d4];
            s += q[4*d4+0]*kv.x + q[4*d4+1]*kv.y + q[4*d4+2]*kv.z + q[4*d4+3]*kv.w;
        }
        s = s * scale + biasS[(r1 - r2 + 7)*15 + (c1 - c2 + 7)];
        bool msk = (mi && (q_r != (r2 < 4))) || (mj && (q_c != (c2 < 4)));
        if (msk) s = -1e30f;
        S[t][j] = s;
        mx = fmaxf(mx, s);
    }
    float sum = 0.f;
#pragma unroll 4
    for (int j = 0; j < 64; j++) {
        float p = __expf(S[t][j] - mx);
        S[t][j] = p;
        sum += p;
    }
    float o[32] = {};
#pragma unroll 2
    for (int j = 0; j < 64; j++) {
        float p = S[t][j];
        const float4* vr = (const float4*)&vs[j][0];
#pragma unroll
        for (int d4 = 0; d4 < 8; d4++) {
            float4 vv = vr[d4];
            o[4*d4+0] += p*vv.x; o[4*d4+1] += p*vv.y;
            o[4*d4+2] += p*vv.z; o[4*d4+3] += p*vv.w;
        }
    }
    float inv = 1.f / sum;
    __nv_bfloat16* orow = ao + (long)(wg*64 + t) * C_ + head*HDIM;
#pragma unroll
    for (int d4 = 0; d4 < 8; d4++) {
        *(__nv_bfloat162*)(orow + 4*d4)     = __floats2bfloat162_rn(o[4*d4]*inv,   o[4*d4+1]*inv);
        *(__nv_bfloat162*)(orow + 4*d4 + 2) = __floats2bfloat162_rn(o[4*d4+2]*inv, o[4*d4+3]*inv);
    }
}

// ---------------- launcher ----------------
extern "C" void kernel_launch(void* const* d_in, const int* in_sizes, int n_in,
                              void* d_out, int out_size) {
    const float* x      = (const float*)d_in[0];
    const float* ln1_g  = (const float*)d_in[1];
    const float* ln1_b  = (const float*)d_in[2];
    const float* qkv_w  = (const float*)d_in[3];
    const float* qkv_b  = (const float*)d_in[4];
    const float* rpp    = (const float*)d_in[5];
    const float* lin_w  = (const float*)d_in[6];
    const float* lin_b  = (const float*)d_in[7];
    const float* ln2_g  = (const float*)d_in[8];
    const float* ln2_b  = (const float*)d_in[9];
    const float* mlp_w1 = (const float*)d_in[10];
    const float* mlp_b1 = (const float*)d_in[11];
    const float* mlp_w2 = (const float*)d_in[12];
    const float* mlp_b2 = (const float*)d_in[13];
    float* out = (float*)d_out;

    __nv_bfloat16 *YZ, *QKV, *Hm, *Wb;
    float *XMID;
    cudaGetSymbolAddress((void**)&YZ,   g_YZ);
    cudaGetSymbolAddress((void**)&QKV,  g_QKV);
    cudaGetSymbolAddress((void**)&XMID, g_XMID);
    cudaGetSymbolAddress((void**)&Hm,   g_H);
    cudaGetSymbolAddress((void**)&Wb,   g_Wb);
    __nv_bfloat16* AO = Hm;   // front NTOK*C_ of g_H, free until mlp1

    // 0) convert weights fp32 -> bf16
    cvt_kernel<<<(QKVW*C_ + 255)/256, 256>>>(qkv_w,  Wb + W_QKV_OFF, QKVW*C_);
    cvt_kernel<<<(C_*C_   + 255)/256, 256>>>(lin_w,  Wb + W_LIN_OFF, C_*C_);
    cvt_kernel<<<(MLPD*C_ + 255)/256, 256>>>(mlp_w1, Wb + W_M1_OFF,  MLPD*C_);
    cvt_kernel<<<(C_*MLPD + 255)/256, 256>>>(mlp_w2, Wb + W_M2_OFF,  C_*MLPD);

    const int LN_BLOCKS = NTOK / 8;
    const int MBT = NTOK / 128;     // 1024 row tiles

    // 1) LN1 + shift-roll + window partition -> bf16
    ln_kernel<true><<<LN_BLOCKS, 256>>>(x, ln1_g, ln1_b, YZ);
    // 2) qkv projection (+bias) -> bf16 QKV
    gemm_bf16<0, __nv_bfloat16><<<dim3(QKVW/64, MBT), 256>>>(
        YZ, Wb + W_QKV_OFF, qkv_b, nullptr, QKV, NTOK, QKVW, C_);
    // 3) windowed attention -> bf16 AO
    attn_kernel<<<dim3(2048, NHEAD), 64>>>(QKV, rpp, AO);
    // 4) output projection + un-window/un-roll + residual -> fp32 XMID
    gemm_bf16<1, float><<<dim3(C_/64, MBT), 256>>>(
        AO, Wb + W_LIN_OFF, lin_b, x, XMID, NTOK, C_, C_);
    // 5) LN2 -> bf16 Z
    ln_kernel<false><<<LN_BLOCKS, 256>>>(XMID, ln2_g, ln2_b, YZ);
    // 6) MLP up + exact GELU -> bf16 H
    gemm_bf16<2, __nv_bfloat16><<<dim3(MLPD/64, MBT), 256>>>(
        YZ, Wb + W_M1_OFF, mlp_b1, nullptr, Hm, NTOK, MLPD, C_);
    // 7) MLP down + residual -> fp32 out
    gemm_bf16<3, float><<<dim3(C_/64, MBT), 256>>>(
        Hm, Wb + W_M2_OFF, mlp_b2, XMID, out, NTOK, C_, MLPD);
}